// round 11
// baseline (speedup 1.0000x reference)
#include <cuda_runtime.h>
#include <cuda_bf16.h>

#define BATCH   4096
#define N_OR    21
#define N_ORN   42
#define N_LN    56
#define N_PN    42
#define N_KC    2000
#define N_ODOR  34
#define NSTEPS  20
#define ALPHA   0.9f
#define VTH     1.0f
#define GSOMA   0.3f
#define ISCALE  0.5f

// PN spike masks per (row, step): bit k = PN neuron k
__device__ unsigned long long g_masks[BATCH * NSTEPS];

// ---- packed f32x2 helpers: ONLY fma.rn.f32x2 (the verified pattern) ----
static __device__ __forceinline__ unsigned long long pk2(float lo, float hi) {
    return (unsigned long long)__float_as_uint(lo)
         | ((unsigned long long)__float_as_uint(hi) << 32);
}
static __device__ __forceinline__ float lo2(unsigned long long v) {
    return __uint_as_float((unsigned)v);
}
static __device__ __forceinline__ float hi2(unsigned long long v) {
    return __uint_as_float((unsigned)(v >> 32));
}
static __device__ __forceinline__ unsigned long long fma2(
    unsigned long long a, unsigned long long b, unsigned long long c) {
    unsigned long long r;
    asm("fma.rn.f32x2 %0,%1,%2,%3;" : "=l"(r) : "l"(a), "l"(b), "l"(c));
    return r;
}
#define ONE2  0x3F8000003F800000ull   /* {1.0f,1.0f} */
#define ZERO2 0x0000000000000000ull

// spread 21-bit value to even bit positions of a 64-bit word
__device__ __forceinline__ unsigned long long spread21(unsigned x) {
    unsigned long long v = x & 0x1FFFFFu;
    v = (v | (v << 16)) & 0x0000FFFF0000FFFFull;
    v = (v | (v << 8))  & 0x00FF00FF00FF00FFull;
    v = (v | (v << 4))  & 0x0F0F0F0F0F0F0F0Full;
    v = (v | (v << 2))  & 0x3333333333333333ull;
    v = (v | (v << 1))  & 0x5555555555555555ull;
    return v;
}

// ---------------------------------------------------------------------------
// Kernel 1: ORN/LN/PN cascade — round-4 proven version.
// One warp per row. ORN 2i,2i+1 share drive -> one state per OR, weight rows
// pair-summed. Complement-sum trick on the LN->PN loop.
// ---------------------------------------------------------------------------
__global__ __launch_bounds__(256) void k1_masks(
    const float* __restrict__ or_input, const float* __restrict__ or_gains,
    const float* __restrict__ orn_to_pn, const float* __restrict__ orn_to_ln,
    const float* __restrict__ ln_to_pn)
{
    __shared__ float2 sOLp[N_OR][32];   // pair-summed orn_to_ln rows (28 used)
    __shared__ float2 sOPp[N_OR][32];   // pair-summed orn_to_pn rows (21 used)
    __shared__ float2 sLP[N_LN][32];    // ln_to_pn rows (21 used)
    __shared__ float2 sLPsum[32];       // column sums of ln_to_pn
    __shared__ float  sSg[N_OR];

    int tid = threadIdx.x;
    for (int i = tid; i < N_OR * 32; i += 256) {
        int p = i >> 5, c = i & 31;
        float2 a = make_float2(0.f, 0.f), b = make_float2(0.f, 0.f);
        if (c < 28) {
            float2 r0 = ((const float2*)(orn_to_ln + (2 * p)     * N_LN))[c];
            float2 r1 = ((const float2*)(orn_to_ln + (2 * p + 1) * N_LN))[c];
            a = make_float2(r0.x + r1.x, r0.y + r1.y);
        }
        if (c < 21) {
            float2 r0 = ((const float2*)(orn_to_pn + (2 * p)     * N_PN))[c];
            float2 r1 = ((const float2*)(orn_to_pn + (2 * p + 1) * N_PN))[c];
            b = make_float2(r0.x + r1.x, r0.y + r1.y);
        }
        sOLp[p][c] = a;
        sOPp[p][c] = b;
    }
    for (int i = tid; i < N_LN * 32; i += 256) {
        int r = i >> 5, c = i & 31;
        sLP[r][c] = (c < 21) ? ((const float2*)(ln_to_pn + r * N_PN))[c]
                             : make_float2(0.f, 0.f);
    }
    if (tid < N_OR) sSg[tid] = log1pf(expf(or_gains[tid]));  // softplus
    __syncthreads();
    if (tid < 32) {
        float sx = 0.f, sy = 0.f;
        for (int r = 0; r < N_LN; r++) { sx += sLP[r][tid].x; sy += sLP[r][tid].y; }
        sLPsum[tid] = make_float2(sx, sy);
    }
    __syncthreads();

    int warp = tid >> 5, lane = tid & 31;
    int row = (blockIdx.x << 3) + warp;

    float d = (lane < N_OR)
            ? or_input[row * N_OR + lane] * sSg[lane] * ISCALE : 0.f;

    float vO = 0.f, vLx = 0.f, vLy = 0.f, vPx = 0.f, vPy = 0.f;
    unsigned long long* mout = g_masks + (size_t)row * NSTEPS;

    for (int t = 0; t < NSTEPS; t++) {
        // ORN LIF (one state per OR pair)
        vO = ALPHA * vO + d;
        bool sO = (vO - VTH) > 0.f;
        unsigned bO = __ballot_sync(0xFFFFFFFFu, sO) & 0x1FFFFFu;
        if (sO) vO = 0.f;

        // merged LN drive + PN excitation over OR-pair spikes
        float aLx = 0.f, aLy = 0.f, eEx = 0.f, eEy = 0.f;
        unsigned m = bO;
        while (m) {
            int p = __ffs(m) - 1; m &= m - 1;
            float2 a = sOLp[p][lane];
            float2 e = sOPp[p][lane];
            aLx += a.x; aLy += a.y; eEx += e.x; eEy += e.y;
        }

        // LN LIF
        vLx = ALPHA * vLx + aLx;
        vLy = ALPHA * vLy + aLy;
        bool sx = (vLx - VTH) > 0.f, sy = (vLy - VTH) > 0.f;
        unsigned bLx = __ballot_sync(0xFFFFFFFFu, sx) & 0x0FFFFFFFu;
        unsigned bLy = __ballot_sync(0xFFFFFFFFu, sy) & 0x0FFFFFFFu;
        if (sx) vLx = 0.f;
        if (sy) vLy = 0.f;

        // LN->PN inhibition: direct or complement (uniform branch)
        float iIx, iIy;
        int nb = __popc(bLx) + __popc(bLy);
        if (nb > 28) {
            iIx = sLPsum[lane].x; iIy = sLPsum[lane].y;
            m = ~bLx & 0x0FFFFFFFu;
            while (m) {
                int p = __ffs(m) - 1; m &= m - 1;
                float2 w = sLP[2 * p][lane];
                iIx -= w.x; iIy -= w.y;
            }
            m = ~bLy & 0x0FFFFFFFu;
            while (m) {
                int p = __ffs(m) - 1; m &= m - 1;
                float2 w = sLP[2 * p + 1][lane];
                iIx -= w.x; iIy -= w.y;
            }
        } else {
            iIx = 0.f; iIy = 0.f;
            m = bLx;
            while (m) {
                int p = __ffs(m) - 1; m &= m - 1;
                float2 w = sLP[2 * p][lane];
                iIx += w.x; iIy += w.y;
            }
            m = bLy;
            while (m) {
                int p = __ffs(m) - 1; m &= m - 1;
                float2 w = sLP[2 * p + 1][lane];
                iIx += w.x; iIy += w.y;
            }
        }

        // PN LIF
        vPx = ALPHA * vPx + eEx - iIx;
        vPy = ALPHA * vPy + eEy - iIy;
        sx = (vPx - VTH) > 0.f; sy = (vPy - VTH) > 0.f;
        unsigned bPx = __ballot_sync(0xFFFFFFFFu, sx) & 0x1FFFFFu;
        unsigned bPy = __ballot_sync(0xFFFFFFFFu, sy) & 0x1FFFFFu;
        if (sx) vPx = 0.f;
        if (sy) vPy = 0.f;

        if (lane == 0)
            mout[t] = spread21(bPx) | (spread21(bPy) << 1);
    }
}

// ---------------------------------------------------------------------------
// Kernel 2: KC dynamics + APL + decode. One CTA/row, 8 KC cols/thread, state
// packed f32x2 (all arithmetic via fma.rn.f32x2 only). Next-step weight rows
// accumulated into vd before the barrier. One barrier/step. Warp-sliced
// deterministic decode — each lane covers odor `lane` AND (lanes 0-1) odor
// `lane+32`, so all 34 odor columns are written (fixes the R9/R10 bug).
// ---------------------------------------------------------------------------
__global__ __launch_bounds__(256, 4) void k2_kc(
    const float* __restrict__ pn_to_kc, const float* __restrict__ kc_to_apl,
    const float* __restrict__ apl_to_kc, const float* __restrict__ dec_w,
    const float* __restrict__ dec_b, float* __restrict__ out)
{
    __shared__ int   sCnt[NSTEPS + 1];
    __shared__ int   sOff[NSTEPS + 1][N_PN];
    __shared__ float sW[2][8];
    __shared__ int   sT0;
    __shared__ int   sWTot[8];
    __shared__ int   sIdx[2048];
    __shared__ float sRate[2048];
    __shared__ float sLg[8][N_ODOR];

    int tid = threadIdx.x;
    int lane = tid & 31, wid = tid >> 5;
    int row = blockIdx.x;

    if (tid < 8) { sW[0][tid] = 0.f; sW[1][tid] = 0.f; }
    if (tid < 32) {
        int n = 0;
        if (tid < NSTEPS) {
            unsigned long long m = g_masks[(size_t)row * NSTEPS + tid];
            while (m) {
                int k = __ffsll((long long)m) - 1; m &= m - 1;
                sOff[tid][n++] = k * (N_KC * 4);   // byte offset of weight row
            }
            sCnt[tid] = n;
        }
        if (tid == NSTEPS) sCnt[NSTEPS] = 0;
        unsigned nz = __ballot_sync(0xFFFFFFFFu, n > 0);
        if (tid == 0) sT0 = nz ? (__ffs(nz) - 1) : NSTEPS;
    }
    __syncthreads();

    int t0 = sT0;
    if (t0 >= NSTEPS) {   // no PN spikes ever -> logits = dec_b
        if (tid < N_ODOR) out[(size_t)row * N_ODOR + tid] = dec_b[tid];
        return;
    }

    int c0 = tid * 8;
    bool valid = (c0 < N_KC);
    const char* wbase = (const char*)(pn_to_kc + (valid ? c0 : 0));
    const float* aplkp = apl_to_kc + (valid ? c0 : 0);
    const float* aplwp = kc_to_apl + (valid ? c0 : 0);

    unsigned long long aplk0 = 0, aplk1 = 0, aplk2 = 0, aplk3 = 0;
    float aplw[8];
    if (valid) {
        aplk0 = pk2(aplkp[0], aplkp[1]);
        aplk1 = pk2(aplkp[2], aplkp[3]);
        aplk2 = pk2(aplkp[4], aplkp[5]);
        aplk3 = pk2(aplkp[6], aplkp[7]);
        #pragma unroll
        for (int j = 0; j < 8; j++) aplw[j] = aplwp[j];
    } else {
        #pragma unroll
        for (int j = 0; j < 8; j++) aplw[j] = 0.f;
    }

    unsigned long long vd0 = 0, vd1 = 0, vd2 = 0, vd3 = 0;
    unsigned long long va0 = 0, va1 = 0, va2 = 0, va3 = 0;
    int cnt[8];
    #pragma unroll
    for (int j = 0; j < 8; j++) cnt[j] = 0;

    const unsigned long long ALPHA2 = pk2(ALPHA, ALPHA);
    const unsigned long long AG2    = pk2(ALPHA - GSOMA, ALPHA - GSOMA);
    const unsigned long long G2     = pk2(GSOMA, GSOMA);

    // prefetch step t0 rows into vd (state is exactly zero before t0)
    if (valid) {
        int n = sCnt[t0];
        for (int i = 0; i < n; i++) {
            int off = sOff[t0][i];
            const float* w = (const float*)(wbase + off);
            vd0 = fma2(ONE2, pk2(w[0], w[1]), vd0);
            vd1 = fma2(ONE2, pk2(w[2], w[3]), vd1);
            vd2 = fma2(ONE2, pk2(w[4], w[5]), vd2);
            vd3 = fma2(ONE2, pk2(w[6], w[7]), vd3);
        }
    }

    for (int t = t0; t < NSTEPS; t++) {
        // APL from previous step (buffer (t+1)&1, zero at t0): fixed-order sum
        const float* wprev = sW[(t + 1) & 1];
        float apl = ((((((wprev[0] + wprev[1]) + wprev[2]) + wprev[3])
                     + wprev[4]) + wprev[5]) + wprev[6]) + wprev[7];

        // vd -= apl * aplk  (apl==0 is an exact no-op)
        unsigned long long napl2 = pk2(-apl, -apl);
        vd0 = fma2(napl2, aplk0, vd0);
        vd1 = fma2(napl2, aplk1, vd1);
        vd2 = fma2(napl2, aplk2, vd2);
        vd3 = fma2(napl2, aplk3, vd3);

        // axon compartment: va = (ALPHA-GSOMA)*va + GSOMA*vd
        va0 = fma2(AG2, va0, fma2(G2, vd0, ZERO2));
        va1 = fma2(AG2, va1, fma2(G2, vd1, ZERO2));
        va2 = fma2(AG2, va2, fma2(G2, vd2, ZERO2));
        va3 = fma2(AG2, va3, fma2(G2, vd3, ZERO2));

        // spike / reset / count / APL partial (scalar)
        float part = 0.f;
        {
            float x, y;
            x = lo2(va0); y = hi2(va0);
            if ((x - VTH) > 0.f) { x = 0.f; cnt[0]++; part += aplw[0]; }
            if ((y - VTH) > 0.f) { y = 0.f; cnt[1]++; part += aplw[1]; }
            va0 = pk2(x, y);
            x = lo2(va1); y = hi2(va1);
            if ((x - VTH) > 0.f) { x = 0.f; cnt[2]++; part += aplw[2]; }
            if ((y - VTH) > 0.f) { y = 0.f; cnt[3]++; part += aplw[3]; }
            va1 = pk2(x, y);
            x = lo2(va2); y = hi2(va2);
            if ((x - VTH) > 0.f) { x = 0.f; cnt[4]++; part += aplw[4]; }
            if ((y - VTH) > 0.f) { y = 0.f; cnt[5]++; part += aplw[5]; }
            va2 = pk2(x, y);
            x = lo2(va3); y = hi2(va3);
            if ((x - VTH) > 0.f) { x = 0.f; cnt[6]++; part += aplw[6]; }
            if ((y - VTH) > 0.f) { y = 0.f; cnt[7]++; part += aplw[7]; }
            va3 = pk2(x, y);
        }
        #pragma unroll
        for (int o = 16; o; o >>= 1)
            part += __shfl_xor_sync(0xFFFFFFFFu, part, o);
        if (lane == 0) sW[t & 1][wid] = part;

        // pre-accumulate next step BEFORE barrier: vd = ALPHA*vd + rows(t+1)
        vd0 = fma2(ALPHA2, vd0, ZERO2);
        vd1 = fma2(ALPHA2, vd1, ZERO2);
        vd2 = fma2(ALPHA2, vd2, ZERO2);
        vd3 = fma2(ALPHA2, vd3, ZERO2);
        int n = sCnt[t + 1];          // sCnt[NSTEPS] == 0
        if (valid) {
            for (int i = 0; i < n; i++) {
                int off = sOff[t + 1][i];
                const float* w = (const float*)(wbase + off);
                vd0 = fma2(ONE2, pk2(w[0], w[1]), vd0);
                vd1 = fma2(ONE2, pk2(w[2], w[3]), vd1);
                vd2 = fma2(ONE2, pk2(w[4], w[5]), vd2);
                vd3 = fma2(ONE2, pk2(w[6], w[7]), vd3);
            }
        }
        __syncthreads();
    }

    // ---- compact active KCs (deterministic, ascending kc index) ----
    int act = 0;
    #pragma unroll
    for (int j = 0; j < 8; j++) if (cnt[j] > 0) act++;

    int x = act;
    #pragma unroll
    for (int dlt = 1; dlt < 32; dlt <<= 1) {
        int y = __shfl_up_sync(0xFFFFFFFFu, x, dlt);
        if (lane >= dlt) x += y;
    }
    if (lane == 31) sWTot[wid] = x;
    __syncthreads();
    int base = 0;
    #pragma unroll
    for (int w = 0; w < 8; w++) if (w < wid) base += sWTot[w];
    int pos = base + x - act;
    #pragma unroll
    for (int j = 0; j < 8; j++) {
        if (cnt[j] > 0) {
            sIdx[pos]  = c0 + j;
            sRate[pos] = (float)cnt[j] * (1.f / NSTEPS);
            pos++;
        }
    }
    __syncthreads();

    // ---- decode split over 8 warps (fixed slices -> deterministic) ----
    // lane covers odor `lane`; lanes 0-1 ALSO cover odors 32-33 (N_ODOR=34).
    int K = 0;
    #pragma unroll
    for (int w = 0; w < 8; w++) K += sWTot[w];
    int per = (K + 7) >> 3;
    int beg = wid * per;
    int end = min(K, beg + per);
    float acc0 = 0.f, acc1 = 0.f;
    for (int i = beg; i < end; i++) {
        float r = sRate[i];
        const float* dw = dec_w + sIdx[i] * N_ODOR;
        acc0 = fmaf(r, __ldg(dw + lane), acc0);
        if (lane < N_ODOR - 32)
            acc1 = fmaf(r, __ldg(dw + 32 + lane), acc1);
    }
    sLg[wid][lane] = acc0;
    if (lane < N_ODOR - 32) sLg[wid][32 + lane] = acc1;
    __syncthreads();
    if (tid < N_ODOR) {
        float su = 0.f;
        #pragma unroll
        for (int w = 0; w < 8; w++) su += sLg[w][tid];
        out[(size_t)row * N_ODOR + tid] = su + dec_b[tid];
    }
}

extern "C" void kernel_launch(void* const* d_in, const int* in_sizes, int n_in,
                              void* d_out, int out_size) {
    const float* or_input  = (const float*)d_in[0];   // [4096, 21]
    const float* or_gains  = (const float*)d_in[1];   // [21]
    // d_in[2] = mapping [21,42] — fixed OR i -> ORN 2i,2i+1 (folded into k1)
    const float* orn_to_pn = (const float*)d_in[3];   // [42, 42]
    const float* orn_to_ln = (const float*)d_in[4];   // [42, 56]
    const float* ln_to_pn  = (const float*)d_in[5];   // [56, 42]
    const float* pn_to_kc  = (const float*)d_in[6];   // [42, 2000]
    const float* kc_to_apl = (const float*)d_in[7];   // [2000, 1]
    const float* apl_to_kc = (const float*)d_in[8];   // [1, 2000]
    const float* dec_w     = (const float*)d_in[9];   // [2000, 34]
    const float* dec_b     = (const float*)d_in[10];  // [34]
    float* out = (float*)d_out;                       // [4096, 34]

    k1_masks<<<BATCH / 8, 256>>>(or_input, or_gains,
                                 orn_to_pn, orn_to_ln, ln_to_pn);
    k2_kc<<<BATCH, 256>>>(pn_to_kc, kc_to_apl, apl_to_kc, dec_w, dec_b, out);
}

// round 12
// speedup vs baseline: 1.0305x; 1.0305x over previous
#include <cuda_runtime.h>
#include <cuda_bf16.h>

#define BATCH   4096
#define N_OR    21
#define N_ORN   42
#define N_LN    56
#define N_PN    42
#define N_KC    2000
#define N_ODOR  34
#define NSTEPS  20
#define ALPHA   0.9f
#define VTH     1.0f
#define GSOMA   0.3f
#define ISCALE  0.5f

// PN spike masks per (row, step): bit k = PN neuron k
__device__ unsigned long long g_masks[BATCH * NSTEPS];

// ---- packed f32x2 helpers: ONLY fma.rn.f32x2 (the verified pattern) ----
static __device__ __forceinline__ unsigned long long pk2(float lo, float hi) {
    return (unsigned long long)__float_as_uint(lo)
         | ((unsigned long long)__float_as_uint(hi) << 32);
}
static __device__ __forceinline__ float lo2(unsigned long long v) {
    return __uint_as_float((unsigned)v);
}
static __device__ __forceinline__ float hi2(unsigned long long v) {
    return __uint_as_float((unsigned)(v >> 32));
}
static __device__ __forceinline__ unsigned long long fma2(
    unsigned long long a, unsigned long long b, unsigned long long c) {
    unsigned long long r;
    asm("fma.rn.f32x2 %0,%1,%2,%3;" : "=l"(r) : "l"(a), "l"(b), "l"(c));
    return r;
}
#define ONE2  0x3F8000003F800000ull   /* {1.0f,1.0f} */
#define ZERO2 0x0000000000000000ull

// spread 21-bit value to even bit positions of a 64-bit word
__device__ __forceinline__ unsigned long long spread21(unsigned x) {
    unsigned long long v = x & 0x1FFFFFu;
    v = (v | (v << 16)) & 0x0000FFFF0000FFFFull;
    v = (v | (v << 8))  & 0x00FF00FF00FF00FFull;
    v = (v | (v << 4))  & 0x0F0F0F0F0F0F0F0Full;
    v = (v | (v << 2))  & 0x3333333333333333ull;
    v = (v | (v << 1))  & 0x5555555555555555ull;
    return v;
}

// ---------------------------------------------------------------------------
// Kernel 1: ORN/LN/PN cascade. One warp per row. ORN 2i,2i+1 share drive ->
// one state per OR, weight rows pair-summed. EXACT mask-result caches:
//  - 2-slot LRU for the ORN-spike loop (ORN masks are near-periodic)
//  - 1-slot for the LN->PN inhibition (LN masks constant in steady state)
// Cache hits reuse bit-identical sums (same order), so results are unchanged.
// ---------------------------------------------------------------------------
__global__ __launch_bounds__(256) void k1_masks(
    const float* __restrict__ or_input, const float* __restrict__ or_gains,
    const float* __restrict__ orn_to_pn, const float* __restrict__ orn_to_ln,
    const float* __restrict__ ln_to_pn)
{
    __shared__ float2 sOLp[N_OR][32];   // pair-summed orn_to_ln rows (28 used)
    __shared__ float2 sOPp[N_OR][32];   // pair-summed orn_to_pn rows (21 used)
    __shared__ float2 sLP[N_LN][32];    // ln_to_pn rows (21 used)
    __shared__ float2 sLPsum[32];       // column sums of ln_to_pn
    __shared__ float  sSg[N_OR];

    int tid = threadIdx.x;
    for (int i = tid; i < N_OR * 32; i += 256) {
        int p = i >> 5, c = i & 31;
        float2 a = make_float2(0.f, 0.f), b = make_float2(0.f, 0.f);
        if (c < 28) {
            float2 r0 = ((const float2*)(orn_to_ln + (2 * p)     * N_LN))[c];
            float2 r1 = ((const float2*)(orn_to_ln + (2 * p + 1) * N_LN))[c];
            a = make_float2(r0.x + r1.x, r0.y + r1.y);
        }
        if (c < 21) {
            float2 r0 = ((const float2*)(orn_to_pn + (2 * p)     * N_PN))[c];
            float2 r1 = ((const float2*)(orn_to_pn + (2 * p + 1) * N_PN))[c];
            b = make_float2(r0.x + r1.x, r0.y + r1.y);
        }
        sOLp[p][c] = a;
        sOPp[p][c] = b;
    }
    for (int i = tid; i < N_LN * 32; i += 256) {
        int r = i >> 5, c = i & 31;
        sLP[r][c] = (c < 21) ? ((const float2*)(ln_to_pn + r * N_PN))[c]
                             : make_float2(0.f, 0.f);
    }
    if (tid < N_OR) sSg[tid] = log1pf(expf(or_gains[tid]));  // softplus
    __syncthreads();
    if (tid < 32) {
        float sx = 0.f, sy = 0.f;
        for (int r = 0; r < N_LN; r++) { sx += sLP[r][tid].x; sy += sLP[r][tid].y; }
        sLPsum[tid] = make_float2(sx, sy);
    }
    __syncthreads();

    int warp = tid >> 5, lane = tid & 31;
    int row = (blockIdx.x << 3) + warp;

    float d = (lane < N_OR)
            ? or_input[row * N_OR + lane] * sSg[lane] * ISCALE : 0.f;

    float vO = 0.f, vLx = 0.f, vLy = 0.f, vPx = 0.f, vPy = 0.f;
    unsigned long long* mout = g_masks + (size_t)row * NSTEPS;

    // ORN-loop cache (2-slot LRU). Sentinel 0xFFFFFFFF can never match a
    // 21-bit mask; mask==0 is a valid, cacheable entry.
    unsigned  cmA = 0xFFFFFFFFu, cmB = 0xFFFFFFFFu;
    float cA_aLx = 0.f, cA_aLy = 0.f, cA_eEx = 0.f, cA_eEy = 0.f;
    float cB_aLx = 0.f, cB_aLy = 0.f, cB_eEx = 0.f, cB_eEy = 0.f;
    int lru = 0;
    // LN-loop cache (1-slot)
    unsigned cLx = 0xFFFFFFFFu, cLy = 0xFFFFFFFFu;
    float cI_x = 0.f, cI_y = 0.f;

    for (int t = 0; t < NSTEPS; t++) {
        // ORN LIF (one state per OR pair)
        vO = ALPHA * vO + d;
        bool sO = (vO - VTH) > 0.f;
        unsigned bO = __ballot_sync(0xFFFFFFFFu, sO) & 0x1FFFFFu;
        if (sO) vO = 0.f;

        // merged LN drive + PN excitation over OR-pair spikes (cached)
        float aLx, aLy, eEx, eEy;
        if (bO == cmA) {
            aLx = cA_aLx; aLy = cA_aLy; eEx = cA_eEx; eEy = cA_eEy;
        } else if (bO == cmB) {
            aLx = cB_aLx; aLy = cB_aLy; eEx = cB_eEx; eEy = cB_eEy;
        } else {
            aLx = 0.f; aLy = 0.f; eEx = 0.f; eEy = 0.f;
            unsigned m = bO;
            while (m) {
                int p = __ffs(m) - 1; m &= m - 1;
                float2 a = sOLp[p][lane];
                float2 e = sOPp[p][lane];
                aLx += a.x; aLy += a.y; eEx += e.x; eEy += e.y;
            }
            if (lru == 0) {
                cmA = bO; cA_aLx = aLx; cA_aLy = aLy; cA_eEx = eEx; cA_eEy = eEy;
            } else {
                cmB = bO; cB_aLx = aLx; cB_aLy = aLy; cB_eEx = eEx; cB_eEy = eEy;
            }
            lru ^= 1;
        }

        // LN LIF
        vLx = ALPHA * vLx + aLx;
        vLy = ALPHA * vLy + aLy;
        bool sx = (vLx - VTH) > 0.f, sy = (vLy - VTH) > 0.f;
        unsigned bLx = __ballot_sync(0xFFFFFFFFu, sx) & 0x0FFFFFFFu;
        unsigned bLy = __ballot_sync(0xFFFFFFFFu, sy) & 0x0FFFFFFFu;
        if (sx) vLx = 0.f;
        if (sy) vLy = 0.f;

        // LN->PN inhibition (cached; complement trick when dense)
        float iIx, iIy;
        if (bLx == cLx && bLy == cLy) {
            iIx = cI_x; iIy = cI_y;
        } else {
            unsigned m;
            int nb = __popc(bLx) + __popc(bLy);
            if (nb > 28) {
                iIx = sLPsum[lane].x; iIy = sLPsum[lane].y;
                m = ~bLx & 0x0FFFFFFFu;
                while (m) {
                    int p = __ffs(m) - 1; m &= m - 1;
                    float2 w = sLP[2 * p][lane];
                    iIx -= w.x; iIy -= w.y;
                }
                m = ~bLy & 0x0FFFFFFFu;
                while (m) {
                    int p = __ffs(m) - 1; m &= m - 1;
                    float2 w = sLP[2 * p + 1][lane];
                    iIx -= w.x; iIy -= w.y;
                }
            } else {
                iIx = 0.f; iIy = 0.f;
                m = bLx;
                while (m) {
                    int p = __ffs(m) - 1; m &= m - 1;
                    float2 w = sLP[2 * p][lane];
                    iIx += w.x; iIy += w.y;
                }
                m = bLy;
                while (m) {
                    int p = __ffs(m) - 1; m &= m - 1;
                    float2 w = sLP[2 * p + 1][lane];
                    iIx += w.x; iIy += w.y;
                }
            }
            cLx = bLx; cLy = bLy; cI_x = iIx; cI_y = iIy;
        }

        // PN LIF
        vPx = ALPHA * vPx + eEx - iIx;
        vPy = ALPHA * vPy + eEy - iIy;
        sx = (vPx - VTH) > 0.f; sy = (vPy - VTH) > 0.f;
        unsigned bPx = __ballot_sync(0xFFFFFFFFu, sx) & 0x1FFFFFu;
        unsigned bPy = __ballot_sync(0xFFFFFFFFu, sy) & 0x1FFFFFu;
        if (sx) vPx = 0.f;
        if (sy) vPy = 0.f;

        if (lane == 0)
            mout[t] = spread21(bPx) | (spread21(bPy) << 1);
    }
}

// ---------------------------------------------------------------------------
// Kernel 2: KC dynamics + APL + decode. One CTA/row, 8 KC cols/thread, state
// packed f32x2 (fma.rn.f32x2 only). Weight rows loaded as 2x float4 (LDG.128).
// Next-step rows accumulated into vd before the barrier. One barrier/step.
// Warp-sliced decode covering all 34 odor columns.
// ---------------------------------------------------------------------------
__global__ __launch_bounds__(256, 4) void k2_kc(
    const float* __restrict__ pn_to_kc, const float* __restrict__ kc_to_apl,
    const float* __restrict__ apl_to_kc, const float* __restrict__ dec_w,
    const float* __restrict__ dec_b, float* __restrict__ out)
{
    __shared__ int   sCnt[NSTEPS + 1];
    __shared__ int   sOff[NSTEPS + 1][N_PN];
    __shared__ float sW[2][8];
    __shared__ int   sT0;
    __shared__ int   sWTot[8];
    __shared__ int   sIdx[2048];
    __shared__ float sRate[2048];
    __shared__ float sLg[8][N_ODOR];

    int tid = threadIdx.x;
    int lane = tid & 31, wid = tid >> 5;
    int row = blockIdx.x;

    if (tid < 8) { sW[0][tid] = 0.f; sW[1][tid] = 0.f; }
    if (tid < 32) {
        int n = 0;
        if (tid < NSTEPS) {
            unsigned long long m = g_masks[(size_t)row * NSTEPS + tid];
            while (m) {
                int k = __ffsll((long long)m) - 1; m &= m - 1;
                sOff[tid][n++] = k * (N_KC * 4);   // byte offset of weight row
            }
            sCnt[tid] = n;
        }
        if (tid == NSTEPS) sCnt[NSTEPS] = 0;
        unsigned nz = __ballot_sync(0xFFFFFFFFu, n > 0);
        if (tid == 0) sT0 = nz ? (__ffs(nz) - 1) : NSTEPS;
    }
    __syncthreads();

    int t0 = sT0;
    if (t0 >= NSTEPS) {   // no PN spikes ever -> logits = dec_b
        if (tid < N_ODOR) out[(size_t)row * N_ODOR + tid] = dec_b[tid];
        return;
    }

    int c0 = tid * 8;
    bool valid = (c0 < N_KC);
    const char* wbase = (const char*)(pn_to_kc + (valid ? c0 : 0));
    const float* aplkp = apl_to_kc + (valid ? c0 : 0);
    const float* aplwp = kc_to_apl + (valid ? c0 : 0);

    unsigned long long aplk0 = 0, aplk1 = 0, aplk2 = 0, aplk3 = 0;
    float aplw[8];
    if (valid) {
        aplk0 = pk2(aplkp[0], aplkp[1]);
        aplk1 = pk2(aplkp[2], aplkp[3]);
        aplk2 = pk2(aplkp[4], aplkp[5]);
        aplk3 = pk2(aplkp[6], aplkp[7]);
        #pragma unroll
        for (int j = 0; j < 8; j++) aplw[j] = aplwp[j];
    } else {
        #pragma unroll
        for (int j = 0; j < 8; j++) aplw[j] = 0.f;
    }

    unsigned long long vd0 = 0, vd1 = 0, vd2 = 0, vd3 = 0;
    unsigned long long va0 = 0, va1 = 0, va2 = 0, va3 = 0;
    int cnt[8];
    #pragma unroll
    for (int j = 0; j < 8; j++) cnt[j] = 0;

    const unsigned long long ALPHA2 = pk2(ALPHA, ALPHA);
    const unsigned long long AG2    = pk2(ALPHA - GSOMA, ALPHA - GSOMA);
    const unsigned long long G2     = pk2(GSOMA, GSOMA);

    // prefetch step t0 rows into vd (state is exactly zero before t0)
    if (valid) {
        int n = sCnt[t0];
        for (int i = 0; i < n; i++) {
            int off = sOff[t0][i];
            float4 a = __ldg((const float4*)(wbase + off));
            float4 b = __ldg((const float4*)(wbase + off + 16));
            vd0 = fma2(ONE2, pk2(a.x, a.y), vd0);
            vd1 = fma2(ONE2, pk2(a.z, a.w), vd1);
            vd2 = fma2(ONE2, pk2(b.x, b.y), vd2);
            vd3 = fma2(ONE2, pk2(b.z, b.w), vd3);
        }
    }

    for (int t = t0; t < NSTEPS; t++) {
        // APL from previous step (buffer (t+1)&1, zero at t0): fixed-order sum
        const float* wprev = sW[(t + 1) & 1];
        float apl = ((((((wprev[0] + wprev[1]) + wprev[2]) + wprev[3])
                     + wprev[4]) + wprev[5]) + wprev[6]) + wprev[7];

        // vd -= apl * aplk  (apl==0 is an exact no-op)
        unsigned long long napl2 = pk2(-apl, -apl);
        vd0 = fma2(napl2, aplk0, vd0);
        vd1 = fma2(napl2, aplk1, vd1);
        vd2 = fma2(napl2, aplk2, vd2);
        vd3 = fma2(napl2, aplk3, vd3);

        // axon compartment: va = (ALPHA-GSOMA)*va + GSOMA*vd
        va0 = fma2(AG2, va0, fma2(G2, vd0, ZERO2));
        va1 = fma2(AG2, va1, fma2(G2, vd1, ZERO2));
        va2 = fma2(AG2, va2, fma2(G2, vd2, ZERO2));
        va3 = fma2(AG2, va3, fma2(G2, vd3, ZERO2));

        // spike / reset / count / APL partial (scalar)
        float part = 0.f;
        {
            float x, y;
            x = lo2(va0); y = hi2(va0);
            if ((x - VTH) > 0.f) { x = 0.f; cnt[0]++; part += aplw[0]; }
            if ((y - VTH) > 0.f) { y = 0.f; cnt[1]++; part += aplw[1]; }
            va0 = pk2(x, y);
            x = lo2(va1); y = hi2(va1);
            if ((x - VTH) > 0.f) { x = 0.f; cnt[2]++; part += aplw[2]; }
            if ((y - VTH) > 0.f) { y = 0.f; cnt[3]++; part += aplw[3]; }
            va1 = pk2(x, y);
            x = lo2(va2); y = hi2(va2);
            if ((x - VTH) > 0.f) { x = 0.f; cnt[4]++; part += aplw[4]; }
            if ((y - VTH) > 0.f) { y = 0.f; cnt[5]++; part += aplw[5]; }
            va2 = pk2(x, y);
            x = lo2(va3); y = hi2(va3);
            if ((x - VTH) > 0.f) { x = 0.f; cnt[6]++; part += aplw[6]; }
            if ((y - VTH) > 0.f) { y = 0.f; cnt[7]++; part += aplw[7]; }
            va3 = pk2(x, y);
        }
        #pragma unroll
        for (int o = 16; o; o >>= 1)
            part += __shfl_xor_sync(0xFFFFFFFFu, part, o);
        if (lane == 0) sW[t & 1][wid] = part;

        // pre-accumulate next step BEFORE barrier: vd = ALPHA*vd + rows(t+1)
        vd0 = fma2(ALPHA2, vd0, ZERO2);
        vd1 = fma2(ALPHA2, vd1, ZERO2);
        vd2 = fma2(ALPHA2, vd2, ZERO2);
        vd3 = fma2(ALPHA2, vd3, ZERO2);
        int n = sCnt[t + 1];          // sCnt[NSTEPS] == 0
        if (valid) {
            for (int i = 0; i < n; i++) {
                int off = sOff[t + 1][i];
                float4 a = __ldg((const float4*)(wbase + off));
                float4 b = __ldg((const float4*)(wbase + off + 16));
                vd0 = fma2(ONE2, pk2(a.x, a.y), vd0);
                vd1 = fma2(ONE2, pk2(a.z, a.w), vd1);
                vd2 = fma2(ONE2, pk2(b.x, b.y), vd2);
                vd3 = fma2(ONE2, pk2(b.z, b.w), vd3);
            }
        }
        __syncthreads();
    }

    // ---- compact active KCs (deterministic, ascending kc index) ----
    int act = 0;
    #pragma unroll
    for (int j = 0; j < 8; j++) if (cnt[j] > 0) act++;

    int x = act;
    #pragma unroll
    for (int dlt = 1; dlt < 32; dlt <<= 1) {
        int y = __shfl_up_sync(0xFFFFFFFFu, x, dlt);
        if (lane >= dlt) x += y;
    }
    if (lane == 31) sWTot[wid] = x;
    __syncthreads();
    int base = 0;
    #pragma unroll
    for (int w = 0; w < 8; w++) if (w < wid) base += sWTot[w];
    int pos = base + x - act;
    #pragma unroll
    for (int j = 0; j < 8; j++) {
        if (cnt[j] > 0) {
            sIdx[pos]  = c0 + j;
            sRate[pos] = (float)cnt[j] * (1.f / NSTEPS);
            pos++;
        }
    }
    __syncthreads();

    // ---- decode split over 8 warps (fixed slices -> deterministic) ----
    // lane covers odor `lane`; lanes 0-1 ALSO cover odors 32-33 (N_ODOR=34).
    int K = 0;
    #pragma unroll
    for (int w = 0; w < 8; w++) K += sWTot[w];
    int per = (K + 7) >> 3;
    int beg = wid * per;
    int end = min(K, beg + per);
    float acc0 = 0.f, acc1 = 0.f;
    for (int i = beg; i < end; i++) {
        float r = sRate[i];
        const float* dw = dec_w + sIdx[i] * N_ODOR;
        acc0 = fmaf(r, __ldg(dw + lane), acc0);
        if (lane < N_ODOR - 32)
            acc1 = fmaf(r, __ldg(dw + 32 + lane), acc1);
    }
    sLg[wid][lane] = acc0;
    if (lane < N_ODOR - 32) sLg[wid][32 + lane] = acc1;
    __syncthreads();
    if (tid < N_ODOR) {
        float su = 0.f;
        #pragma unroll
        for (int w = 0; w < 8; w++) su += sLg[w][tid];
        out[(size_t)row * N_ODOR + tid] = su + dec_b[tid];
    }
}

extern "C" void kernel_launch(void* const* d_in, const int* in_sizes, int n_in,
                              void* d_out, int out_size) {
    const float* or_input  = (const float*)d_in[0];   // [4096, 21]
    const float* or_gains  = (const float*)d_in[1];   // [21]
    // d_in[2] = mapping [21,42] — fixed OR i -> ORN 2i,2i+1 (folded into k1)
    const float* orn_to_pn = (const float*)d_in[3];   // [42, 42]
    const float* orn_to_ln = (const float*)d_in[4];   // [42, 56]
    const float* ln_to_pn  = (const float*)d_in[5];   // [56, 42]
    const float* pn_to_kc  = (const float*)d_in[6];   // [42, 2000]
    const float* kc_to_apl = (const float*)d_in[7];   // [2000, 1]
    const float* apl_to_kc = (const float*)d_in[8];   // [1, 2000]
    const float* dec_w     = (const float*)d_in[9];   // [2000, 34]
    const float* dec_b     = (const float*)d_in[10];  // [34]
    float* out = (float*)d_out;                       // [4096, 34]

    k1_masks<<<BATCH / 8, 256>>>(or_input, or_gains,
                                 orn_to_pn, orn_to_ln, ln_to_pn);
    k2_kc<<<BATCH, 256>>>(pn_to_kc, kc_to_apl, apl_to_kc, dec_w, dec_b, out);
}